// round 15
// baseline (speedup 1.0000x reference)
#include <cuda_runtime.h>
#include <cuda_bf16.h>

// Problem constants: B=32, T=1024, F=4, C=256, S=256, MAX_DUR=8 (durations <= 7)
#define BQ 32
#define TQ 1024
#define FQ 4
#define CQ 256
#define SQ 256
#define ROW_VEC 256   // one frame row [F=4][C=256] = 1024 floats = 256 float4

// ---------------------------------------------------------------------------
// Fused kernel, 2 segments per block to amortize the DRAM-silent prologue.
// Grid: 4096 blocks (= B * S/2), 256 threads.
// Phase 1: one in-block inclusive scan of the batch's 256 durations
//          (serves both segments).
// Phase 2: R8 body x2 interleaved: thread tid accumulates float4 #tid of each
//          frame row for BOTH segments -> up to 16 independent LDG.128 in
//          flight per thread; single barrier; the two segments' freq-reduce
//          and stores run in parallel on threads 0-63 / 64-127.
//
// Dtype: reference declares int64 but JAX w/o x64 downcasts to int32; detect
// on device via high words (all zero <=> int64; P(false pos)=8^-32).
// ---------------------------------------------------------------------------
__global__ __launch_bounds__(256, 6) void fused_kernel(const float4* __restrict__ e4,
                                                       const int* __restrict__ dur_raw,
                                                       float4* __restrict__ out4) {
    __shared__ int sh_cum[SQ];
    __shared__ int warp_tot[8];
    __shared__ int s_is64;
    __shared__ float4 sh[2][CQ];   // 8 KB

    const int blk = blockIdx.x;
    const int b   = blk >> 7;          // batch (128 blocks per batch)
    const int g   = blk & 127;         // segment pair index
    const int tid = threadIdx.x;
    const int lane = tid & 31;
    const int w    = tid >> 5;

    // --- dtype probe (first 32 candidate int64 high words of whole array) ---
    if (tid < 32) {
        int v = dur_raw[2 * tid + 1];
        unsigned m = __ballot_sync(0xffffffffu, v != 0);
        if (tid == 0) s_is64 = (m == 0u) ? 1 : 0;
    }
    __syncthreads();

    // --- phase 1: inclusive scan of batch b's durations (tid = phone id) ---
    int d = s_is64 ? dur_raw[(b * SQ + tid) * 2]    // low word of LE int64
                   : dur_raw[b * SQ + tid];

    int x = d;
    #pragma unroll
    for (int off = 1; off < 32; off <<= 1) {
        int y = __shfl_up_sync(0xffffffffu, x, off);
        if (lane >= off) x += y;
    }
    if (lane == 31) warp_tot[w] = x;
    __syncthreads();

    int base = 0;
    #pragma unroll
    for (int i = 0; i < 8; ++i)
        if (i < w) base += warp_tot[i];

    sh_cum[tid] = base + x;
    __syncthreads();

    // --- phase 2: segments s0 = 2g, s1 = 2g+1 ---
    const int s0 = g << 1;
    const int c_m1 = (s0 == 0) ? 0 : sh_cum[s0 - 1];
    const int c_0  = sh_cum[s0];
    const int c_1  = sh_cum[s0 + 1];

    const int start0 = min(c_m1, TQ);
    const int cnt0   = min(c_0, TQ) - start0;
    const int start1 = min(c_0, TQ);
    const int cnt1   = min(c_1, TQ) - start1;

    const float4* p0 = e4 + (size_t)(b * TQ + start0) * ROW_VEC + tid;
    const float4* p1 = e4 + (size_t)(b * TQ + start1) * ROW_VEC + tid;

    float4 acc0 = make_float4(0.f, 0.f, 0.f, 0.f);
    float4 acc1 = acc0;
    #pragma unroll
    for (int t = 0; t < 8; ++t) {
        if (t < cnt0) {
            float4 v = __ldcs(p0 + t * ROW_VEC);
            acc0.x += v.x; acc0.y += v.y; acc0.z += v.z; acc0.w += v.w;
        }
        if (t < cnt1) {
            float4 v = __ldcs(p1 + t * ROW_VEC);
            acc1.x += v.x; acc1.y += v.y; acc1.z += v.z; acc1.w += v.w;
        }
    }
    sh[0][tid] = acc0;
    sh[1][tid] = acc1;
    __syncthreads();

    // --- epilogue: both segments reduced in parallel (threads 0-127) ---
    if (tid < 128) {
        const int seg  = tid >> 6;           // 0 or 1
        const int l    = tid & 63;           // c-group
        float4 a  = sh[seg][l];
        float4 b1 = sh[seg][l + 64];
        float4 b2 = sh[seg][l + 128];
        float4 b3 = sh[seg][l + 192];
        const int cnt = seg ? cnt1 : cnt0;
        const float inv = (cnt > 0) ? 1.0f / (float)(cnt * FQ) : 0.0f;
        float4 r;
        r.x = ((a.x + b1.x) + (b2.x + b3.x)) * inv;
        r.y = ((a.y + b1.y) + (b2.y + b3.y)) * inv;
        r.z = ((a.z + b1.z) + (b2.z + b3.z)) * inv;
        r.w = ((a.w + b1.w) + (b2.w + b3.w)) * inv;
        __stcs(out4 + ((size_t)(b * SQ + s0 + seg)) * 64 + l, r);
    }
}

extern "C" void kernel_launch(void* const* d_in, const int* in_sizes, int n_in,
                              void* d_out, int out_size) {
    const float4* e_src = (const float4*)d_in[0];   // [B, T, F, C] float32
    const int*    d_src = (const int*)d_in[1];      // [B, S] int64-or-int32 (detected)
    float4* out = (float4*)d_out;                   // [B, S, C] float32

    fused_kernel<<<BQ * (SQ / 2), 256>>>(e_src, d_src, out);
}

// round 16
// speedup vs baseline: 1.0206x; 1.0206x over previous
#include <cuda_runtime.h>
#include <cuda_bf16.h>

// Problem constants: B=32, T=1024, F=4, C=256, S=256, MAX_DUR=8 (durations <= 7)
#define BQ 32
#define TQ 1024
#define FQ 4
#define CQ 256
#define SQ 256
#define ROW_VEC 256   // one frame row [F=4][C=256] = 1024 floats = 256 float4

// ---------------------------------------------------------------------------
// Fused kernel, warp-autonomous phase 2 (no barrier / no smem after scan).
// Grid: 2048 blocks (= B * S/4), 256 threads = 8 warps.
// Phase 1: one in-block inclusive scan of the batch's 256 durations.
// Phase 2: warp w handles (segment s = g*4 + (w>>1), half h = w&1).
//   Lane l owns float4 column h*32+l of the frame row for ALL 4 freq bins:
//   per frame 4 independent LDG.128 at +0/+64/+128/+192 float4s; frame loop
//   unrolled to 8 predicated iterations -> up to 28 independent LDG.128 per
//   warp. Freq reduction is entirely in-lane (a0+a1+a2+a3); one coalesced
//   STG.128 per warp. Warps retire independently (no epilogue serialization).
//
// Dtype: reference declares int64 but JAX w/o x64 downcasts to int32; detect
// on device via high words (all zero <=> int64; P(false pos)=8^-32).
// ---------------------------------------------------------------------------
__global__ __launch_bounds__(256, 5) void fused_kernel(const float4* __restrict__ e4,
                                                       const int* __restrict__ dur_raw,
                                                       float4* __restrict__ out4) {
    __shared__ int sh_cum[SQ];
    __shared__ int warp_tot[8];
    __shared__ int s_is64;

    const int blk = blockIdx.x;
    const int b   = blk >> 6;          // batch (64 blocks per batch)
    const int g   = blk & 63;          // 4-segment group within batch
    const int tid = threadIdx.x;
    const int lane = tid & 31;
    const int w    = tid >> 5;

    // --- dtype probe (first 32 candidate int64 high words of whole array) ---
    if (tid < 32) {
        int v = dur_raw[2 * tid + 1];
        unsigned m = __ballot_sync(0xffffffffu, v != 0);
        if (tid == 0) s_is64 = (m == 0u) ? 1 : 0;
    }
    __syncthreads();

    // --- phase 1: inclusive scan of batch b's durations (tid = phone id) ---
    int d = s_is64 ? dur_raw[(b * SQ + tid) * 2]    // low word of LE int64
                   : dur_raw[b * SQ + tid];

    int x = d;
    #pragma unroll
    for (int off = 1; off < 32; off <<= 1) {
        int y = __shfl_up_sync(0xffffffffu, x, off);
        if (lane >= off) x += y;
    }
    if (lane == 31) warp_tot[w] = x;
    __syncthreads();

    int base = 0;
    #pragma unroll
    for (int i = 0; i < 8; ++i)
        if (i < w) base += warp_tot[i];

    sh_cum[tid] = base + x;
    __syncthreads();

    // --- phase 2: warp-autonomous. warp w -> segment s, half h ---
    const int s = (g << 2) + (w >> 1);
    const int h = w & 1;

    const int incl  = sh_cum[s];
    const int excl  = (s == 0) ? 0 : sh_cum[s - 1];
    const int start = min(excl, TQ);
    const int cnt   = min(incl, TQ) - start;

    const float4* p = e4 + (size_t)(b * TQ + start) * ROW_VEC + (h << 5) + lane;

    float4 a0 = make_float4(0.f, 0.f, 0.f, 0.f);
    float4 a1 = a0, a2 = a0, a3 = a0;

    #pragma unroll
    for (int t = 0; t < 8; ++t) {
        if (t < cnt) {
            const float4* q = p + t * ROW_VEC;
            float4 v0 = __ldcs(q);          // f = 0
            float4 v1 = __ldcs(q + 64);     // f = 1
            float4 v2 = __ldcs(q + 128);    // f = 2
            float4 v3 = __ldcs(q + 192);    // f = 3
            a0.x += v0.x; a0.y += v0.y; a0.z += v0.z; a0.w += v0.w;
            a1.x += v1.x; a1.y += v1.y; a1.z += v1.z; a1.w += v1.w;
            a2.x += v2.x; a2.y += v2.y; a2.z += v2.z; a2.w += v2.w;
            a3.x += v3.x; a3.y += v3.y; a3.z += v3.z; a3.w += v3.w;
        }
    }

    const float inv = (cnt > 0) ? 1.0f / (float)(cnt * FQ) : 0.0f;
    float4 r;
    r.x = ((a0.x + a1.x) + (a2.x + a3.x)) * inv;
    r.y = ((a0.y + a1.y) + (a2.y + a3.y)) * inv;
    r.z = ((a0.z + a1.z) + (a2.z + a3.z)) * inv;
    r.w = ((a0.w + a1.w) + (a2.w + a3.w)) * inv;
    __stcs(out4 + (size_t)(b * SQ + s) * 64 + (h << 5) + lane, r);
}

extern "C" void kernel_launch(void* const* d_in, const int* in_sizes, int n_in,
                              void* d_out, int out_size) {
    const float4* e_src = (const float4*)d_in[0];   // [B, T, F, C] float32
    const int*    d_src = (const int*)d_in[1];      // [B, S] int64-or-int32 (detected)
    float4* out = (float4*)d_out;                   // [B, S, C] float32

    fused_kernel<<<BQ * (SQ / 4), 256>>>(e_src, d_src, out);
}